// round 1
// baseline (speedup 1.0000x reference)
#include <cuda_runtime.h>
#include <math_constants.h>
#include <cstdint>

// Problem constants
#define BB   2
#define TT   2048
#define CC   1024
#define HH   16
#define DD   64
#define NTOK (BB * TT)      // 4096 rows
#define QKVN (3 * CC)       // 3072 qkv cols

// Scratch (no cudaMalloc allowed): qkv activations + attention output
__device__ float g_qkv[(size_t)NTOK * QKVN];  // [4096, 3072] row-major (q|k|v)
__device__ float g_att[(size_t)NTOK * CC];    // [4096, 1024] = y before proj

// ---------------------------------------------------------------------------
// SGEMM with bias: C[M,N] = A[M,K] @ B[K,N] + bias[N]
// BM=BN=128, BK=8, 256 threads, 8x8 per thread, warp tile 32x64.
// ---------------------------------------------------------------------------
__global__ __launch_bounds__(256) void sgemm_bias_kernel(
    const float* __restrict__ A, const float* __restrict__ Bm,
    const float* __restrict__ bias, float* __restrict__ Cm,
    int M, int N, int K)
{
    const int BM = 128, BN = 128, BK = 8;
    __shared__ float As[BK][BM];   // transposed A tile
    __shared__ float Bs[BK][BN];

    const int tid  = threadIdx.x;
    const int m0   = blockIdx.y * BM;
    const int n0   = blockIdx.x * BN;

    const int warp = tid >> 5;
    const int lane = tid & 31;
    const int wm   = warp >> 1;          // 0..3  (M dir, 32 rows each)
    const int wn   = warp & 1;           // 0..1  (N dir, 64 cols each)
    const int lr   = lane >> 3;          // 0..3
    const int lc   = lane & 7;           // 0..7
    const int rbase = wm * 32 + lr * 8;  // row offset within tile
    const int cbase = wn * 64 + lc * 8;  // col offset within tile

    // Global->smem load mapping (one float4 each for A and B per thread)
    const int arow = tid >> 1;            // 0..127
    const int ac   = (tid & 1) * 4;       // 0 or 4
    const int brow = tid >> 5;            // 0..7
    const int bc   = (tid & 31) * 4;      // 0..124

    const float* Aptr = A  + (size_t)(m0 + arow) * K + ac;
    const float* Bptr = Bm + (size_t)brow * N + n0 + bc;

    float acc[8][8];
#pragma unroll
    for (int i = 0; i < 8; i++)
#pragma unroll
        for (int j = 0; j < 8; j++) acc[i][j] = 0.0f;

    for (int k0 = 0; k0 < K; k0 += BK) {
        float4 av = *(const float4*)(Aptr + k0);
        float4 bv = *(const float4*)(Bptr + (size_t)k0 * N);
        As[ac + 0][arow] = av.x;
        As[ac + 1][arow] = av.y;
        As[ac + 2][arow] = av.z;
        As[ac + 3][arow] = av.w;
        *(float4*)&Bs[brow][bc] = bv;
        __syncthreads();

#pragma unroll
        for (int k = 0; k < BK; k++) {
            float af[8], bf[8];
            *(float4*)&af[0] = *(const float4*)&As[k][rbase];
            *(float4*)&af[4] = *(const float4*)&As[k][rbase + 4];
            *(float4*)&bf[0] = *(const float4*)&Bs[k][cbase];
            *(float4*)&bf[4] = *(const float4*)&Bs[k][cbase + 4];
#pragma unroll
            for (int i = 0; i < 8; i++)
#pragma unroll
                for (int j = 0; j < 8; j++)
                    acc[i][j] += af[i] * bf[j];
        }
        __syncthreads();
    }

    // Epilogue: add bias, float4 stores
#pragma unroll
    for (int i = 0; i < 8; i++) {
        size_t row = (size_t)(m0 + rbase + i);
        float* crow = Cm + row * N + n0 + cbase;
        const float* brow_p = bias + n0 + cbase;
#pragma unroll
        for (int jv = 0; jv < 2; jv++) {
            float4 bvv = *(const float4*)(brow_p + jv * 4);
            float4 ov;
            ov.x = acc[i][jv * 4 + 0] + bvv.x;
            ov.y = acc[i][jv * 4 + 1] + bvv.y;
            ov.z = acc[i][jv * 4 + 2] + bvv.z;
            ov.w = acc[i][jv * 4 + 3] + bvv.w;
            *(float4*)(crow + jv * 4) = ov;
        }
    }
}

// ---------------------------------------------------------------------------
// Flash attention (fp32, causal). One block = one (b,h) and one 64-row q tile.
// 256 threads; thread (ty,tx) owns rows {ty+16i} and cols {tx+16j}, i,j<4.
// This interleaved mapping makes all compute-phase LDS conflict-free (pad 65).
// ---------------------------------------------------------------------------
__global__ __launch_bounds__(256) void flash_attn_kernel(
    const float* __restrict__ qkv, float* __restrict__ y)
{
    extern __shared__ float sm[];
    float (*Qs)[65] = (float(*)[65])(sm);
    float (*Ks)[65] = (float(*)[65])(sm + 64 * 65);
    float (*Ps)[65] = (float(*)[65])(sm + 2 * 64 * 65);
    float (*Vs)[64] = (float(*)[64])(sm + 3 * 64 * 65);

    const int tid = threadIdx.x;
    const int ty  = tid >> 4;   // 0..15
    const int tx  = tid & 15;   // 0..15

    const int bh = blockIdx.y;
    const int b  = bh >> 4;
    const int h  = bh & 15;
    const int qt = gridDim.x - 1 - blockIdx.x;  // big (late) q tiles launch first

    const float* base = qkv + (size_t)b * TT * QKVN + h * DD;

    // Load Q tile [64 x 64] (rows qt*64..qt*64+63)
    for (int idx = tid; idx < 64 * 16; idx += 256) {
        int rr = idx >> 4;
        int dv = (idx & 15) << 2;
        float4 v = *(const float4*)(base + (size_t)(qt * 64 + rr) * QKVN + dv);
        Qs[rr][dv + 0] = v.x; Qs[rr][dv + 1] = v.y;
        Qs[rr][dv + 2] = v.z; Qs[rr][dv + 3] = v.w;
    }

    float m_i[4], l_i[4], o[4][4];
#pragma unroll
    for (int i = 0; i < 4; i++) {
        m_i[i] = -CUDART_INF_F;
        l_i[i] = 0.0f;
#pragma unroll
        for (int j = 0; j < 4; j++) o[i][j] = 0.0f;
    }

    for (int kt = 0; kt <= qt; kt++) {
        __syncthreads();   // guard Ks/Vs against prior-iter PV readers
        // Load K and V tiles
        for (int idx = tid; idx < 64 * 16; idx += 256) {
            int rr = idx >> 4;
            int dv = (idx & 15) << 2;
            const float* kp = base + CC + (size_t)(kt * 64 + rr) * QKVN + dv;
            float4 kv = *(const float4*)kp;
            Ks[rr][dv + 0] = kv.x; Ks[rr][dv + 1] = kv.y;
            Ks[rr][dv + 2] = kv.z; Ks[rr][dv + 3] = kv.w;
            float4 vv = *(const float4*)(kp + CC);
            *(float4*)&Vs[rr][dv] = vv;
        }
        __syncthreads();

        // S = Q K^T * scale
        float s[4][4];
#pragma unroll
        for (int i = 0; i < 4; i++)
#pragma unroll
            for (int j = 0; j < 4; j++) s[i][j] = 0.0f;

#pragma unroll 8
        for (int d = 0; d < 64; d++) {
            float af[4], bf[4];
#pragma unroll
            for (int i = 0; i < 4; i++) af[i] = Qs[ty + 16 * i][d];
#pragma unroll
            for (int j = 0; j < 4; j++) bf[j] = Ks[tx + 16 * j][d];
#pragma unroll
            for (int i = 0; i < 4; i++)
#pragma unroll
                for (int j = 0; j < 4; j++)
                    s[i][j] += af[i] * bf[j];
        }

        const float scale = 0.125f;  // 1/sqrt(64)
#pragma unroll
        for (int i = 0; i < 4; i++)
#pragma unroll
            for (int j = 0; j < 4; j++) s[i][j] *= scale;

        if (kt == qt) {
            // diagonal tile: mask cols > rows (local indices suffice)
#pragma unroll
            for (int i = 0; i < 4; i++)
#pragma unroll
                for (int j = 0; j < 4; j++)
                    if ((tx + 16 * j) > (ty + 16 * i)) s[i][j] = -CUDART_INF_F;
        }

        // Online softmax per row; then write P to smem
#pragma unroll
        for (int i = 0; i < 4; i++) {
            float rm = s[i][0];
#pragma unroll
            for (int j = 1; j < 4; j++) rm = fmaxf(rm, s[i][j]);
#pragma unroll
            for (int off = 8; off > 0; off >>= 1)
                rm = fmaxf(rm, __shfl_xor_sync(0xffffffffu, rm, off));
            float mn    = fmaxf(m_i[i], rm);
            float alpha = __expf(m_i[i] - mn);
            float rs = 0.0f;
#pragma unroll
            for (int j = 0; j < 4; j++) {
                float p = __expf(s[i][j] - mn);
                s[i][j] = p;
                rs += p;
            }
#pragma unroll
            for (int off = 8; off > 0; off >>= 1)
                rs += __shfl_xor_sync(0xffffffffu, rs, off);
            l_i[i] = l_i[i] * alpha + rs;
            m_i[i] = mn;
#pragma unroll
            for (int j = 0; j < 4; j++) {
                o[i][j] *= alpha;
                Ps[ty + 16 * i][tx + 16 * j] = s[i][j];
            }
        }
        __syncthreads();

        // O += P @ V
#pragma unroll 8
        for (int jj = 0; jj < 64; jj++) {
            float pf[4], vf[4];
#pragma unroll
            for (int i = 0; i < 4; i++) pf[i] = Ps[ty + 16 * i][jj];
#pragma unroll
            for (int j = 0; j < 4; j++) vf[j] = Vs[jj][tx + 16 * j];
#pragma unroll
            for (int i = 0; i < 4; i++)
#pragma unroll
                for (int j = 0; j < 4; j++)
                    o[i][j] += pf[i] * vf[j];
        }
    }

    // Normalize and write y in [B, T, C] layout (head h -> cols h*64..h*64+63)
#pragma unroll
    for (int i = 0; i < 4; i++) {
        float inv_l = 1.0f / l_i[i];
        size_t row = (size_t)(b * TT + qt * 64 + ty + 16 * i);
#pragma unroll
        for (int j = 0; j < 4; j++) {
            y[row * CC + h * DD + tx + 16 * j] = o[i][j] * inv_l;
        }
    }
}

// ---------------------------------------------------------------------------
// Launch
// ---------------------------------------------------------------------------
extern "C" void kernel_launch(void* const* d_in, const int* in_sizes, int n_in,
                              void* d_out, int out_size)
{
    (void)in_sizes; (void)n_in; (void)out_size;
    const float* x      = (const float*)d_in[0];   // [B, T, C]
    const float* w_attn = (const float*)d_in[1];   // [C, 3C]
    const float* b_attn = (const float*)d_in[2];   // [3C]
    const float* w_proj = (const float*)d_in[3];   // [C, C]
    const float* b_proj = (const float*)d_in[4];   // [C]
    float* out = (float*)d_out;                    // [B, T, C]

    float* qkv = nullptr;
    float* att = nullptr;
    cudaGetSymbolAddress((void**)&qkv, g_qkv);
    cudaGetSymbolAddress((void**)&att, g_att);

    // 1) QKV GEMM: [4096,1024] @ [1024,3072] + b  -> g_qkv
    {
        dim3 grid(QKVN / 128, NTOK / 128);
        sgemm_bias_kernel<<<grid, 256>>>(x, w_attn, b_attn, qkv,
                                         NTOK, QKVN, CC);
    }

    // 2) Flash attention -> g_att  ([B,T,C] layout)
    {
        const int smem_bytes = (3 * 64 * 65 + 64 * 64) * (int)sizeof(float); // 66304
        cudaFuncSetAttribute(flash_attn_kernel,
                             cudaFuncAttributeMaxDynamicSharedMemorySize,
                             smem_bytes);
        dim3 grid(TT / 64, BB * HH);
        flash_attn_kernel<<<grid, 256, smem_bytes>>>(qkv, att);
    }

    // 3) Proj GEMM: [4096,1024] @ [1024,1024] + b -> out
    {
        dim3 grid(CC / 128, NTOK / 128);
        sgemm_bias_kernel<<<grid, 256>>>(att, w_proj, b_proj, out,
                                         NTOK, CC, CC);
    }
}

// round 3
// speedup vs baseline: 1.3770x; 1.3770x over previous
#include <cuda_runtime.h>
#include <cuda_bf16.h>
#include <math_constants.h>
#include <cstdint>

// Problem constants
#define BB   2
#define TT   2048
#define CC   1024
#define HH   16
#define DD   64
#define NTOK (BB * TT)      // 4096
#define QKVN (3 * CC)       // 3072

// ---------------------------------------------------------------------------
// Scratch (no cudaMalloc allowed)
// ---------------------------------------------------------------------------
__device__ float g_qkv[(size_t)NTOK * QKVN];   // qkv activations fp32
__device__ float g_att[(size_t)NTOK * CC];     // attention output fp32
__device__ __nv_bfloat16 g_xhi[(size_t)NTOK * CC], g_xlo[(size_t)NTOK * CC];
__device__ __nv_bfloat16 g_wahi[(size_t)QKVN * CC], g_walo[(size_t)QKVN * CC]; // [N,K]
__device__ __nv_bfloat16 g_wphi[(size_t)CC * CC],   g_wplo[(size_t)CC * CC];   // [N,K]
__device__ __nv_bfloat16 g_ahi[(size_t)NTOK * CC],  g_alo[(size_t)NTOK * CC];

// ---------------------------------------------------------------------------
// PTX helpers (all plain-sm_103-legal: mma.sync / ldmatrix / cp.async)
// ---------------------------------------------------------------------------
__device__ __forceinline__ uint32_t smem_u32(const void* p) {
    uint32_t a;
    asm("{ .reg .u64 t; cvta.to.shared.u64 t, %1; cvt.u32.u64 %0, t; }"
        : "=r"(a) : "l"(p));
    return a;
}
__device__ __forceinline__ void ldm_x4(uint32_t* r, uint32_t addr) {
    asm volatile("ldmatrix.sync.aligned.m8n8.x4.shared.b16 {%0,%1,%2,%3}, [%4];"
                 : "=r"(r[0]), "=r"(r[1]), "=r"(r[2]), "=r"(r[3]) : "r"(addr));
}
__device__ __forceinline__ void mma16816(float* d, const uint32_t* a, const uint32_t* b) {
    asm volatile(
        "mma.sync.aligned.m16n8k16.row.col.f32.bf16.bf16.f32 "
        "{%0,%1,%2,%3}, {%4,%5,%6,%7}, {%8,%9}, {%0,%1,%2,%3};"
        : "+f"(d[0]), "+f"(d[1]), "+f"(d[2]), "+f"(d[3])
        : "r"(a[0]), "r"(a[1]), "r"(a[2]), "r"(a[3]), "r"(b[0]), "r"(b[1]));
}
__device__ __forceinline__ void cp_async16(uint32_t sa, const void* g) {
    asm volatile("cp.async.ca.shared.global [%0], [%1], 16;" :: "r"(sa), "l"(g));
}
#define CP_COMMIT()  asm volatile("cp.async.commit_group;" ::: "memory")
#define CP_WAIT(n)   asm volatile("cp.async.wait_group %0;" :: "n"(n) : "memory")

// ---------------------------------------------------------------------------
// fp32 -> (bf16 hi, bf16 lo) elementwise split
// ---------------------------------------------------------------------------
__global__ void split_fp32_kernel(const float* __restrict__ in,
                                  __nv_bfloat16* __restrict__ hi,
                                  __nv_bfloat16* __restrict__ lo, int n4) {
    int i = blockIdx.x * blockDim.x + threadIdx.x;
    if (i >= n4) return;
    float4 v = ((const float4*)in)[i];
    float vv[4] = {v.x, v.y, v.z, v.w};
    ushort4 sh, sl;
    unsigned short* ph = &sh.x;
    unsigned short* pl = &sl.x;
#pragma unroll
    for (int j = 0; j < 4; j++) {
        __nv_bfloat16 h = __float2bfloat16(vv[j]);
        __nv_bfloat16 l = __float2bfloat16(vv[j] - __bfloat162float(h));
        ph[j] = __bfloat16_as_ushort(h);
        pl[j] = __bfloat16_as_ushort(l);
    }
    ((ushort4*)hi)[i] = sh;
    ((ushort4*)lo)[i] = sl;
}

// ---------------------------------------------------------------------------
// fp32 [K,N] -> transposed bf16 hi/lo [N,K]
// ---------------------------------------------------------------------------
__global__ void split_transpose_kernel(const float* __restrict__ in,
                                       __nv_bfloat16* __restrict__ hi,
                                       __nv_bfloat16* __restrict__ lo,
                                       int K, int N) {
    __shared__ float tile[32][33];
    int bx = blockIdx.x * 32;  // N offset
    int by = blockIdx.y * 32;  // K offset
    int tx = threadIdx.x, ty = threadIdx.y;
#pragma unroll
    for (int i = 0; i < 32; i += 8)
        tile[ty + i][tx] = in[(size_t)(by + ty + i) * N + bx + tx];
    __syncthreads();
#pragma unroll
    for (int i = 0; i < 32; i += 8) {
        float v = tile[tx][ty + i];
        __nv_bfloat16 h = __float2bfloat16(v);
        __nv_bfloat16 l = __float2bfloat16(v - __bfloat162float(h));
        size_t o = (size_t)(bx + ty + i) * K + by + tx;
        hi[o] = h;
        lo[o] = l;
    }
}

// ---------------------------------------------------------------------------
// Split-bf16 mma.sync GEMM: C[M,N] = A[M,K] @ B[N,K]^T + bias[N]
// 128x128 CTA tile, BK=32, 8 warps (warp tile 64x32), cp.async double buffer.
// smem tiles padded to 80B rows (conflict-free ldmatrix).
// ---------------------------------------------------------------------------
#define GROWB   80                       // padded row stride (bytes) for 32 bf16
#define TILE_B  (128 * GROWB)            // 10240 bytes per sub-tile
#define STAGE_B (4 * TILE_B)             // Ahi|Alo|Bhi|Blo = 40960
#define GEMM_SMEM (2 * STAGE_B + 128)

__global__ __launch_bounds__(256, 1) void gemm_mma_kernel(
    const __nv_bfloat16* __restrict__ Ahi, const __nv_bfloat16* __restrict__ Alo,
    const __nv_bfloat16* __restrict__ Bhi, const __nv_bfloat16* __restrict__ Blo,
    const float* __restrict__ bias, float* __restrict__ Cm,
    int M, int N, int K)
{
    extern __shared__ char dsm[];
    const uint32_t dynb = smem_u32(dsm);
    const uint32_t sb_u = (dynb + 127) & ~127u;
    char* sbase = dsm + (sb_u - dynb);

    const int tid  = threadIdx.x;
    const int wid  = tid >> 5;
    const int lane = tid & 31;
    const int wm   = wid >> 2;          // 0..1 : 64 rows
    const int wn   = wid & 3;           // 0..3 : 32 cols
    const int m0 = blockIdx.y * 128;
    const int n0 = blockIdx.x * 128;

    const int lrow = lane & 15;         // ldmatrix row within 16
    const int lcol8 = (lane >> 4) << 3; // +8 col for mats 2,3

    float acc[4][4][4];
#pragma unroll
    for (int a = 0; a < 4; a++)
#pragma unroll
        for (int b = 0; b < 4; b++)
#pragma unroll
            for (int c = 0; c < 4; c++) acc[a][b][c] = 0.0f;

    const int nCh = K >> 5;   // BK=32

    auto load_stage = [&](int c, int s) {
        char* st = sbase + s * STAGE_B;
        const int kc = c << 5;
#pragma unroll
        for (int it = 0; it < 8; it++) {
            int i    = it * 256 + tid;   // 0..2047
            int tile = i >> 9;           // 0..3
            int w    = i & 511;
            int row  = w >> 2;           // 0..127
            int slot = w & 3;            // 16B slot
            const __nv_bfloat16* gp;
            if      (tile == 0) gp = Ahi + (size_t)(m0 + row) * K + kc + slot * 8;
            else if (tile == 1) gp = Alo + (size_t)(m0 + row) * K + kc + slot * 8;
            else if (tile == 2) gp = Bhi + (size_t)(n0 + row) * K + kc + slot * 8;
            else                gp = Blo + (size_t)(n0 + row) * K + kc + slot * 8;
            uint32_t sa = sb_u + s * STAGE_B + tile * TILE_B + row * GROWB + slot * 16;
            cp_async16(sa, gp);
        }
        CP_COMMIT();
        (void)st;
    };

    auto compute = [&](int s) {
        const uint32_t aHi = sb_u + s * STAGE_B;
        const uint32_t aLo = aHi + TILE_B;
        const uint32_t bHi = aHi + 2 * TILE_B;
        const uint32_t bLo = aHi + 3 * TILE_B;
#pragma unroll
        for (int ks = 0; ks < 2; ks++) {
            const int kb = (ks * 16 + lcol8) * 2;   // byte col offset for this lane
            uint32_t ahi[4][4], alo[4][4], bhi[4][2], blo[4][2];
#pragma unroll
            for (int mf = 0; mf < 4; mf++) {
                int row = wm * 64 + mf * 16 + lrow;
                ldm_x4(ahi[mf], aHi + row * GROWB + kb);
                ldm_x4(alo[mf], aLo + row * GROWB + kb);
            }
#pragma unroll
            for (int bg = 0; bg < 2; bg++) {
                int row = wn * 32 + bg * 16 + lrow;
                uint32_t t[4];
                ldm_x4(t, bHi + row * GROWB + kb);
                bhi[bg * 2][0] = t[0]; bhi[bg * 2 + 1][0] = t[1];
                bhi[bg * 2][1] = t[2]; bhi[bg * 2 + 1][1] = t[3];
                ldm_x4(t, bLo + row * GROWB + kb);
                blo[bg * 2][0] = t[0]; blo[bg * 2 + 1][0] = t[1];
                blo[bg * 2][1] = t[2]; blo[bg * 2 + 1][1] = t[3];
            }
#pragma unroll
            for (int mf = 0; mf < 4; mf++)
#pragma unroll
                for (int nf = 0; nf < 4; nf++) {
                    mma16816(acc[mf][nf], ahi[mf], bhi[nf]);
                    mma16816(acc[mf][nf], ahi[mf], blo[nf]);
                    mma16816(acc[mf][nf], alo[mf], bhi[nf]);
                }
        }
    };

    load_stage(0, 0);
    for (int c = 0; c < nCh; c++) {
        const int s = c & 1;
        __syncthreads();   // all warps done with buffer s^1 before overwrite
        if (c + 1 < nCh) {
            load_stage(c + 1, s ^ 1);
            CP_WAIT(1);    // stage s loads complete (one group may stay pending)
        } else {
            CP_WAIT(0);
        }
        __syncthreads();
        compute(s);
    }

    // Epilogue: add bias, store fp32 (float2 per c-pair)
    const int g = lane >> 2;
    const int t2 = (lane & 3) * 2;
#pragma unroll
    for (int mf = 0; mf < 4; mf++) {
#pragma unroll
        for (int nf = 0; nf < 4; nf++) {
            int col = n0 + wn * 32 + nf * 8 + t2;
            float2 bv = *(const float2*)(bias + col);
            int r0 = m0 + wm * 64 + mf * 16 + g;
            float2 o0 = {acc[mf][nf][0] + bv.x, acc[mf][nf][1] + bv.y};
            float2 o1 = {acc[mf][nf][2] + bv.x, acc[mf][nf][3] + bv.y};
            *(float2*)(Cm + (size_t)r0 * N + col)       = o0;
            *(float2*)(Cm + (size_t)(r0 + 8) * N + col) = o1;
        }
    }
}

// ---------------------------------------------------------------------------
// Flash attention (fp32, causal) — unchanged (passed R1)
// ---------------------------------------------------------------------------
__global__ __launch_bounds__(256) void flash_attn_kernel(
    const float* __restrict__ qkv, float* __restrict__ y)
{
    extern __shared__ float sm[];
    float (*Qs)[65] = (float(*)[65])(sm);
    float (*Ks)[65] = (float(*)[65])(sm + 64 * 65);
    float (*Ps)[65] = (float(*)[65])(sm + 2 * 64 * 65);
    float (*Vs)[64] = (float(*)[64])(sm + 3 * 64 * 65);

    const int tid = threadIdx.x;
    const int ty  = tid >> 4;
    const int tx  = tid & 15;

    const int bh = blockIdx.y;
    const int b  = bh >> 4;
    const int h  = bh & 15;
    const int qt = gridDim.x - 1 - blockIdx.x;

    const float* base = qkv + (size_t)b * TT * QKVN + h * DD;

    for (int idx = tid; idx < 64 * 16; idx += 256) {
        int rr = idx >> 4;
        int dv = (idx & 15) << 2;
        float4 v = *(const float4*)(base + (size_t)(qt * 64 + rr) * QKVN + dv);
        Qs[rr][dv + 0] = v.x; Qs[rr][dv + 1] = v.y;
        Qs[rr][dv + 2] = v.z; Qs[rr][dv + 3] = v.w;
    }

    float m_i[4], l_i[4], o[4][4];
#pragma unroll
    for (int i = 0; i < 4; i++) {
        m_i[i] = -CUDART_INF_F;
        l_i[i] = 0.0f;
#pragma unroll
        for (int j = 0; j < 4; j++) o[i][j] = 0.0f;
    }

    for (int kt = 0; kt <= qt; kt++) {
        __syncthreads();
        for (int idx = tid; idx < 64 * 16; idx += 256) {
            int rr = idx >> 4;
            int dv = (idx & 15) << 2;
            const float* kp = base + CC + (size_t)(kt * 64 + rr) * QKVN + dv;
            float4 kv = *(const float4*)kp;
            Ks[rr][dv + 0] = kv.x; Ks[rr][dv + 1] = kv.y;
            Ks[rr][dv + 2] = kv.z; Ks[rr][dv + 3] = kv.w;
            float4 vv = *(const float4*)(kp + CC);
            *(float4*)&Vs[rr][dv] = vv;
        }
        __syncthreads();

        float s[4][4];
#pragma unroll
        for (int i = 0; i < 4; i++)
#pragma unroll
            for (int j = 0; j < 4; j++) s[i][j] = 0.0f;

#pragma unroll 8
        for (int d = 0; d < 64; d++) {
            float af[4], bf[4];
#pragma unroll
            for (int i = 0; i < 4; i++) af[i] = Qs[ty + 16 * i][d];
#pragma unroll
            for (int j = 0; j < 4; j++) bf[j] = Ks[tx + 16 * j][d];
#pragma unroll
            for (int i = 0; i < 4; i++)
#pragma unroll
                for (int j = 0; j < 4; j++)
                    s[i][j] += af[i] * bf[j];
        }

        const float scale = 0.125f;
#pragma unroll
        for (int i = 0; i < 4; i++)
#pragma unroll
            for (int j = 0; j < 4; j++) s[i][j] *= scale;

        if (kt == qt) {
#pragma unroll
            for (int i = 0; i < 4; i++)
#pragma unroll
                for (int j = 0; j < 4; j++)
                    if ((tx + 16 * j) > (ty + 16 * i)) s[i][j] = -CUDART_INF_F;
        }

#pragma unroll
        for (int i = 0; i < 4; i++) {
            float rm = s[i][0];
#pragma unroll
            for (int j = 1; j < 4; j++) rm = fmaxf(rm, s[i][j]);
#pragma unroll
            for (int off = 8; off > 0; off >>= 1)
                rm = fmaxf(rm, __shfl_xor_sync(0xffffffffu, rm, off));
            float mn    = fmaxf(m_i[i], rm);
            float alpha = __expf(m_i[i] - mn);
            float rs = 0.0f;
#pragma unroll
            for (int j = 0; j < 4; j++) {
                float p = __expf(s[i][j] - mn);
                s[i][j] = p;
                rs += p;
            }
#pragma unroll
            for (int off = 8; off > 0; off >>= 1)
                rs += __shfl_xor_sync(0xffffffffu, rs, off);
            l_i[i] = l_i[i] * alpha + rs;
            m_i[i] = mn;
#pragma unroll
            for (int j = 0; j < 4; j++) {
                o[i][j] *= alpha;
                Ps[ty + 16 * i][tx + 16 * j] = s[i][j];
            }
        }
        __syncthreads();

#pragma unroll 8
        for (int jj = 0; jj < 64; jj++) {
            float pf[4], vf[4];
#pragma unroll
            for (int i = 0; i < 4; i++) pf[i] = Ps[ty + 16 * i][jj];
#pragma unroll
            for (int j = 0; j < 4; j++) vf[j] = Vs[jj][tx + 16 * j];
#pragma unroll
            for (int i = 0; i < 4; i++)
#pragma unroll
                for (int j = 0; j < 4; j++)
                    o[i][j] += pf[i] * vf[j];
        }
    }

#pragma unroll
    for (int i = 0; i < 4; i++) {
        float inv_l = 1.0f / l_i[i];
        size_t row = (size_t)(b * TT + qt * 64 + ty + 16 * i);
#pragma unroll
        for (int j = 0; j < 4; j++) {
            y[row * CC + h * DD + tx + 16 * j] = o[i][j] * inv_l;
        }
    }
}

// ---------------------------------------------------------------------------
// Launch
// ---------------------------------------------------------------------------
extern "C" void kernel_launch(void* const* d_in, const int* in_sizes, int n_in,
                              void* d_out, int out_size)
{
    (void)in_sizes; (void)n_in; (void)out_size;
    const float* x      = (const float*)d_in[0];
    const float* w_attn = (const float*)d_in[1];
    const float* b_attn = (const float*)d_in[2];
    const float* w_proj = (const float*)d_in[3];
    const float* b_proj = (const float*)d_in[4];
    float* out = (float*)d_out;

    float *qkv, *att;
    __nv_bfloat16 *xhi, *xlo, *wahi, *walo, *wphi, *wplo, *ahi, *alo;
    cudaGetSymbolAddress((void**)&qkv,  g_qkv);
    cudaGetSymbolAddress((void**)&att,  g_att);
    cudaGetSymbolAddress((void**)&xhi,  g_xhi);
    cudaGetSymbolAddress((void**)&xlo,  g_xlo);
    cudaGetSymbolAddress((void**)&wahi, g_wahi);
    cudaGetSymbolAddress((void**)&walo, g_walo);
    cudaGetSymbolAddress((void**)&wphi, g_wphi);
    cudaGetSymbolAddress((void**)&wplo, g_wplo);
    cudaGetSymbolAddress((void**)&ahi,  g_ahi);
    cudaGetSymbolAddress((void**)&alo,  g_alo);

    cudaFuncSetAttribute(gemm_mma_kernel,
                         cudaFuncAttributeMaxDynamicSharedMemorySize, GEMM_SMEM);

    // 1) split x -> bf16 hi/lo
    {
        int n4 = NTOK * CC / 4;
        split_fp32_kernel<<<(n4 + 255) / 256, 256>>>(x, xhi, xlo, n4);
    }
    // 2) split+transpose weights -> [N,K] bf16 hi/lo
    {
        dim3 blk(32, 8);
        split_transpose_kernel<<<dim3(QKVN / 32, CC / 32), blk>>>(w_attn, wahi, walo, CC, QKVN);
        split_transpose_kernel<<<dim3(CC / 32, CC / 32), blk>>>(w_proj, wphi, wplo, CC, CC);
    }
    // 3) QKV GEMM (mma.sync): [4096,1024] @ [3072,1024]^T + b -> g_qkv
    {
        dim3 grid(QKVN / 128, NTOK / 128);
        gemm_mma_kernel<<<grid, 256, GEMM_SMEM>>>(xhi, xlo, wahi, walo,
                                                  b_attn, qkv, NTOK, QKVN, CC);
    }
    // 4) flash attention -> g_att
    {
        const int smem_bytes = (3 * 64 * 65 + 64 * 64) * (int)sizeof(float);
        cudaFuncSetAttribute(flash_attn_kernel,
                             cudaFuncAttributeMaxDynamicSharedMemorySize, smem_bytes);
        dim3 grid(TT / 64, BB * HH);
        flash_attn_kernel<<<grid, 256, smem_bytes>>>(qkv, att);
    }
    // 5) split attention output
    {
        int n4 = NTOK * CC / 4;
        split_fp32_kernel<<<(n4 + 255) / 256, 256>>>(att, ahi, alo, n4);
    }
    // 6) proj GEMM (mma.sync): [4096,1024] @ [1024,1024]^T + b -> out
    {
        dim3 grid(CC / 128, NTOK / 128);
        gemm_mma_kernel<<<grid, 256, GEMM_SMEM>>>(ahi, alo, wphi, wplo,
                                                  b_proj, out, NTOK, CC, CC);
    }
}

// round 4
// speedup vs baseline: 2.6179x; 1.9012x over previous
#include <cuda_runtime.h>
#include <cuda_bf16.h>
#include <math_constants.h>
#include <cstdint>

// Problem constants
#define BB   2
#define TT   2048
#define CC   1024
#define HH   16
#define DD   64
#define NTOK (BB * TT)      // 4096
#define QKVN (3 * CC)       // 3072

// ---------------------------------------------------------------------------
// Scratch (no cudaMalloc allowed)
// ---------------------------------------------------------------------------
__device__ __nv_bfloat16 g_xhi[(size_t)NTOK * CC],  g_xlo[(size_t)NTOK * CC];
__device__ __nv_bfloat16 g_wahi[(size_t)QKVN * CC], g_walo[(size_t)QKVN * CC]; // [N,K]
__device__ __nv_bfloat16 g_wphi[(size_t)CC * CC],   g_wplo[(size_t)CC * CC];   // [N,K]
__device__ __nv_bfloat16 g_qkvhi[(size_t)NTOK * QKVN], g_qkvlo[(size_t)NTOK * QKVN];
__device__ __nv_bfloat16 g_ahi[(size_t)NTOK * CC],  g_alo[(size_t)NTOK * CC];

// ---------------------------------------------------------------------------
// PTX helpers (plain-sm_103-legal: mma.sync / ldmatrix / cp.async)
// ---------------------------------------------------------------------------
__device__ __forceinline__ uint32_t smem_u32(const void* p) {
    uint32_t a;
    asm("{ .reg .u64 t; cvta.to.shared.u64 t, %1; cvt.u32.u64 %0, t; }"
        : "=r"(a) : "l"(p));
    return a;
}
__device__ __forceinline__ void ldm_x4(uint32_t* r, uint32_t addr) {
    asm volatile("ldmatrix.sync.aligned.m8n8.x4.shared.b16 {%0,%1,%2,%3}, [%4];"
                 : "=r"(r[0]), "=r"(r[1]), "=r"(r[2]), "=r"(r[3]) : "r"(addr));
}
__device__ __forceinline__ void ldm_x4_t(uint32_t* r, uint32_t addr) {
    asm volatile("ldmatrix.sync.aligned.m8n8.x4.trans.shared.b16 {%0,%1,%2,%3}, [%4];"
                 : "=r"(r[0]), "=r"(r[1]), "=r"(r[2]), "=r"(r[3]) : "r"(addr));
}
__device__ __forceinline__ void mma16816(float* d, const uint32_t* a, const uint32_t* b) {
    asm volatile(
        "mma.sync.aligned.m16n8k16.row.col.f32.bf16.bf16.f32 "
        "{%0,%1,%2,%3}, {%4,%5,%6,%7}, {%8,%9}, {%0,%1,%2,%3};"
        : "+f"(d[0]), "+f"(d[1]), "+f"(d[2]), "+f"(d[3])
        : "r"(a[0]), "r"(a[1]), "r"(a[2]), "r"(a[3]), "r"(b[0]), "r"(b[1]));
}
__device__ __forceinline__ void cp_async16(uint32_t sa, const void* g) {
    asm volatile("cp.async.ca.shared.global [%0], [%1], 16;" :: "r"(sa), "l"(g));
}
#define CP_COMMIT()  asm volatile("cp.async.commit_group;" ::: "memory")
#define CP_WAIT(n)   asm volatile("cp.async.wait_group %0;" :: "n"(n) : "memory")

// pack two fp32 into bf16x2 (lo = first arg in low half)
__device__ __forceinline__ uint32_t pack_bf2(float lo, float hi) {
    uint32_t r;
    asm("cvt.rn.bf16x2.f32 %0, %1, %2;" : "=r"(r) : "f"(hi), "f"(lo));
    return r;
}
__device__ __forceinline__ float bf_res(float v) {
    return v - __bfloat162float(__float2bfloat16(v));
}

// ---------------------------------------------------------------------------
// fp32 -> (bf16 hi, bf16 lo) elementwise split
// ---------------------------------------------------------------------------
__global__ void split_fp32_kernel(const float* __restrict__ in,
                                  __nv_bfloat16* __restrict__ hi,
                                  __nv_bfloat16* __restrict__ lo, int n4) {
    int i = blockIdx.x * blockDim.x + threadIdx.x;
    if (i >= n4) return;
    float4 v = ((const float4*)in)[i];
    float vv[4] = {v.x, v.y, v.z, v.w};
    ushort4 sh, sl;
    unsigned short* ph = &sh.x;
    unsigned short* pl = &sl.x;
#pragma unroll
    for (int j = 0; j < 4; j++) {
        __nv_bfloat16 h = __float2bfloat16(vv[j]);
        __nv_bfloat16 l = __float2bfloat16(vv[j] - __bfloat162float(h));
        ph[j] = __bfloat16_as_ushort(h);
        pl[j] = __bfloat16_as_ushort(l);
    }
    ((ushort4*)hi)[i] = sh;
    ((ushort4*)lo)[i] = sl;
}

// ---------------------------------------------------------------------------
// fp32 [K,N] -> transposed bf16 hi/lo [N,K]
// ---------------------------------------------------------------------------
__global__ void split_transpose_kernel(const float* __restrict__ in,
                                       __nv_bfloat16* __restrict__ hi,
                                       __nv_bfloat16* __restrict__ lo,
                                       int K, int N) {
    __shared__ float tile[32][33];
    int bx = blockIdx.x * 32;
    int by = blockIdx.y * 32;
    int tx = threadIdx.x, ty = threadIdx.y;
#pragma unroll
    for (int i = 0; i < 32; i += 8)
        tile[ty + i][tx] = in[(size_t)(by + ty + i) * N + bx + tx];
    __syncthreads();
#pragma unroll
    for (int i = 0; i < 32; i += 8) {
        float v = tile[tx][ty + i];
        __nv_bfloat16 h = __float2bfloat16(v);
        __nv_bfloat16 l = __float2bfloat16(v - __bfloat162float(h));
        size_t o = (size_t)(bx + ty + i) * K + by + tx;
        hi[o] = h;
        lo[o] = l;
    }
}

// ---------------------------------------------------------------------------
// Split-bf16 mma.sync GEMM: C[M,N] = A[M,K] @ B[N,K]^T + bias[N]
// Output either fp32 (Cf) or split bf16 hi/lo (Chi/Clo) when Chi != nullptr.
// ---------------------------------------------------------------------------
#define GROWB   80
#define TILE_B  (128 * GROWB)
#define STAGE_B (4 * TILE_B)
#define GEMM_SMEM (2 * STAGE_B + 128)

__global__ __launch_bounds__(256, 1) void gemm_mma_kernel(
    const __nv_bfloat16* __restrict__ Ahi, const __nv_bfloat16* __restrict__ Alo,
    const __nv_bfloat16* __restrict__ Bhi, const __nv_bfloat16* __restrict__ Blo,
    const float* __restrict__ bias, float* __restrict__ Cf,
    __nv_bfloat16* __restrict__ Chi, __nv_bfloat16* __restrict__ Clo,
    int M, int N, int K)
{
    extern __shared__ char dsm[];
    const uint32_t dynb = smem_u32(dsm);
    const uint32_t sb_u = (dynb + 127) & ~127u;

    const int tid  = threadIdx.x;
    const int wid  = tid >> 5;
    const int lane = tid & 31;
    const int wm   = wid >> 2;
    const int wn   = wid & 3;
    const int m0 = blockIdx.y * 128;
    const int n0 = blockIdx.x * 128;

    const int lrow = lane & 15;
    const int lcol8 = (lane >> 4) << 3;

    float acc[4][4][4];
#pragma unroll
    for (int a = 0; a < 4; a++)
#pragma unroll
        for (int b = 0; b < 4; b++)
#pragma unroll
            for (int c = 0; c < 4; c++) acc[a][b][c] = 0.0f;

    const int nCh = K >> 5;

    auto load_stage = [&](int c, int s) {
        const int kc = c << 5;
#pragma unroll
        for (int it = 0; it < 8; it++) {
            int i    = it * 256 + tid;
            int tile = i >> 9;
            int w    = i & 511;
            int row  = w >> 2;
            int slot = w & 3;
            const __nv_bfloat16* gp;
            if      (tile == 0) gp = Ahi + (size_t)(m0 + row) * K + kc + slot * 8;
            else if (tile == 1) gp = Alo + (size_t)(m0 + row) * K + kc + slot * 8;
            else if (tile == 2) gp = Bhi + (size_t)(n0 + row) * K + kc + slot * 8;
            else                gp = Blo + (size_t)(n0 + row) * K + kc + slot * 8;
            uint32_t sa = sb_u + s * STAGE_B + tile * TILE_B + row * GROWB + slot * 16;
            cp_async16(sa, gp);
        }
        CP_COMMIT();
    };

    auto compute = [&](int s) {
        const uint32_t aHi = sb_u + s * STAGE_B;
        const uint32_t aLo = aHi + TILE_B;
        const uint32_t bHi = aHi + 2 * TILE_B;
        const uint32_t bLo = aHi + 3 * TILE_B;
#pragma unroll
        for (int ks = 0; ks < 2; ks++) {
            const int kb = (ks * 16 + lcol8) * 2;
            uint32_t ahi[4][4], alo[4][4], bhi[4][2], blo[4][2];
#pragma unroll
            for (int mf = 0; mf < 4; mf++) {
                int row = wm * 64 + mf * 16 + lrow;
                ldm_x4(ahi[mf], aHi + row * GROWB + kb);
                ldm_x4(alo[mf], aLo + row * GROWB + kb);
            }
#pragma unroll
            for (int bg = 0; bg < 2; bg++) {
                int row = wn * 32 + bg * 16 + lrow;
                uint32_t t[4];
                ldm_x4(t, bHi + row * GROWB + kb);
                bhi[bg * 2][0] = t[0]; bhi[bg * 2 + 1][0] = t[1];
                bhi[bg * 2][1] = t[2]; bhi[bg * 2 + 1][1] = t[3];
                ldm_x4(t, bLo + row * GROWB + kb);
                blo[bg * 2][0] = t[0]; blo[bg * 2 + 1][0] = t[1];
                blo[bg * 2][1] = t[2]; blo[bg * 2 + 1][1] = t[3];
            }
#pragma unroll
            for (int mf = 0; mf < 4; mf++)
#pragma unroll
                for (int nf = 0; nf < 4; nf++) {
                    mma16816(acc[mf][nf], ahi[mf], bhi[nf]);
                    mma16816(acc[mf][nf], ahi[mf], blo[nf]);
                    mma16816(acc[mf][nf], alo[mf], bhi[nf]);
                }
        }
    };

    load_stage(0, 0);
    for (int c = 0; c < nCh; c++) {
        const int s = c & 1;
        __syncthreads();
        if (c + 1 < nCh) {
            load_stage(c + 1, s ^ 1);
            CP_WAIT(1);
        } else {
            CP_WAIT(0);
        }
        __syncthreads();
        compute(s);
    }

    const int g = lane >> 2;
    const int t2 = (lane & 3) * 2;
#pragma unroll
    for (int mf = 0; mf < 4; mf++) {
#pragma unroll
        for (int nf = 0; nf < 4; nf++) {
            int col = n0 + wn * 32 + nf * 8 + t2;
            float2 bv = *(const float2*)(bias + col);
            int r0 = m0 + wm * 64 + mf * 16 + g;
            float v0 = acc[mf][nf][0] + bv.x, v1 = acc[mf][nf][1] + bv.y;
            float v2 = acc[mf][nf][2] + bv.x, v3 = acc[mf][nf][3] + bv.y;
            if (Chi) {
                size_t i0 = ((size_t)r0 * N + col) >> 1;
                size_t i1 = ((size_t)(r0 + 8) * N + col) >> 1;
                ((uint32_t*)Chi)[i0] = pack_bf2(v0, v1);
                ((uint32_t*)Clo)[i0] = pack_bf2(bf_res(v0), bf_res(v1));
                ((uint32_t*)Chi)[i1] = pack_bf2(v2, v3);
                ((uint32_t*)Clo)[i1] = pack_bf2(bf_res(v2), bf_res(v3));
            } else {
                float2 o0 = {v0, v1}, o1 = {v2, v3};
                *(float2*)(Cf + (size_t)r0 * N + col)       = o0;
                *(float2*)(Cf + (size_t)(r0 + 8) * N + col) = o1;
            }
        }
    }
}

// ---------------------------------------------------------------------------
// Tensor-core flash attention (causal), split-bf16 3-term on QK^T and PV.
// CTA = (b, h, 128-row q tile); 8 warps x 16 q rows; K/V tiles of 128 keys.
// smem tiles 128 rows x 128B with XOR-16B swizzle (conflict-free ldmatrix).
// ---------------------------------------------------------------------------
#define FT_TILE 16384                       // 128 x 64 bf16
#define FT_STAGE (4 * FT_TILE)              // Khi|Klo|Vhi|Vlo
#define FLASH_SMEM (2 * FT_TILE + 2 * FT_STAGE + 128)   // Q(hi,lo) + 2 stages

__device__ __forceinline__ uint32_t swz(uint32_t base, int row, int bytecol) {
    return base + row * 128 + ((((bytecol >> 4) ^ (row & 7)) << 4));
}

__global__ __launch_bounds__(256, 1) void flash_mma_kernel(
    const __nv_bfloat16* __restrict__ qkvhi,
    const __nv_bfloat16* __restrict__ qkvlo,
    __nv_bfloat16* __restrict__ ohi,
    __nv_bfloat16* __restrict__ olo)
{
    extern __shared__ char dsm[];
    const uint32_t dynb = smem_u32(dsm);
    const uint32_t sb_u = (dynb + 127) & ~127u;
    const uint32_t qhiS = sb_u;
    const uint32_t qloS = sb_u + FT_TILE;
    const uint32_t stgS = sb_u + 2 * FT_TILE;

    const int tid  = threadIdx.x;
    const int wid  = tid >> 5;
    const int lane = tid & 31;
    const int lrow = lane & 15;
    const int lc16 = (lane >> 4) << 4;   // +16 bytes (8 cols) for lanes >= 16
    const int g    = lane >> 2;
    const int t2   = (lane & 3) * 2;

    const int b  = blockIdx.y >> 4;
    const int h  = blockIdx.y & 15;
    const int qt = (int)gridDim.x - 1 - (int)blockIdx.x;

    const size_t rowQ = (size_t)(b * TT + qt * 128);
    const int qcol = h * DD;             // q col base
    const int kcol = CC + h * DD;
    const int vcol = 2 * CC + h * DD;

    // ---- load Q (hi, lo) ----
#pragma unroll
    for (int it = 0; it < 8; it++) {
        int i = it * 256 + tid;          // 0..2047
        int t = i >> 10;                 // 0 = hi, 1 = lo
        int w = i & 1023;
        int r = w >> 3, c = w & 7;
        const __nv_bfloat16* src = (t ? qkvlo : qkvhi)
            + (rowQ + r) * QKVN + qcol + c * 8;
        cp_async16(swz(t ? qloS : qhiS, r, c * 16), src);
    }
    // ---- load K/V stage 0 ----
    auto load_stage = [&](int kt, int s) {
        const size_t rowK = (size_t)(b * TT + kt * 128);
        const uint32_t st = stgS + s * FT_STAGE;
#pragma unroll
        for (int it = 0; it < 16; it++) {
            int i = it * 256 + tid;      // 0..4095
            int t = i >> 10;             // 0..3 : Khi, Klo, Vhi, Vlo
            int w = i & 1023;
            int r = w >> 3, c = w & 7;
            const __nv_bfloat16* base = (t & 1) ? qkvlo : qkvhi;
            int colb = (t < 2) ? kcol : vcol;
            cp_async16(swz(st + t * FT_TILE, r, c * 16),
                       base + (rowK + r) * QKVN + colb + c * 8);
        }
        CP_COMMIT();
    };
    load_stage(0, 0);
    CP_COMMIT();   // Q + stage0 grouped (Q issued before stage0's commit; extra empty group harmless)

    float o[8][4];
#pragma unroll
    for (int nd = 0; nd < 8; nd++)
#pragma unroll
        for (int c = 0; c < 4; c++) o[nd][c] = 0.0f;
    float m0 = -CUDART_INF_F, m1 = -CUDART_INF_F;
    float l0 = 0.0f, l1 = 0.0f;

    for (int kt = 0; kt <= qt; kt++) {
        const int s = kt & 1;
        if (kt + 1 <= qt) {
            load_stage(kt + 1, s ^ 1);
            CP_WAIT(1);
        } else {
            CP_WAIT(0);
        }
        __syncthreads();

        const uint32_t khiS = stgS + s * FT_STAGE;
        const uint32_t kloS = khiS + FT_TILE;
        const uint32_t vhiS = khiS + 2 * FT_TILE;
        const uint32_t vloS = khiS + 3 * FT_TILE;

        // ---- S = Q K^T (3-term split) ----
        float sc[16][4];
#pragma unroll
        for (int nf = 0; nf < 16; nf++)
#pragma unroll
            for (int c = 0; c < 4; c++) sc[nf][c] = 0.0f;

#pragma unroll
        for (int ks = 0; ks < 4; ks++) {
            const int kb = ks * 32 + lc16;
            uint32_t qh[4], ql[4];
            ldm_x4(qh, swz(qhiS, wid * 16 + lrow, kb));
            ldm_x4(ql, swz(qloS, wid * 16 + lrow, kb));
#pragma unroll
            for (int kf = 0; kf < 8; kf++) {
                uint32_t t[4], u[4];
                ldm_x4(t, swz(khiS, kf * 16 + lrow, kb));
                ldm_x4(u, swz(kloS, kf * 16 + lrow, kb));
                uint32_t bh0[2] = {t[0], t[2]}, bh1[2] = {t[1], t[3]};
                uint32_t bl0[2] = {u[0], u[2]}, bl1[2] = {u[1], u[3]};
                mma16816(sc[2 * kf],     qh, bh0);
                mma16816(sc[2 * kf],     qh, bl0);
                mma16816(sc[2 * kf],     ql, bh0);
                mma16816(sc[2 * kf + 1], qh, bh1);
                mma16816(sc[2 * kf + 1], qh, bl1);
                mma16816(sc[2 * kf + 1], ql, bh1);
            }
        }

        // ---- scale + causal mask + online softmax ----
        const float scale = 0.125f;
        const int rl0 = wid * 16 + g;        // local q rows
        const int rl1 = rl0 + 8;
        float rm0 = -CUDART_INF_F, rm1 = -CUDART_INF_F;
#pragma unroll
        for (int nf = 0; nf < 16; nf++) {
            float c0 = sc[nf][0] * scale, c1 = sc[nf][1] * scale;
            float c2 = sc[nf][2] * scale, c3 = sc[nf][3] * scale;
            if (kt == qt) {
                int col = nf * 8 + t2;
                if (col     > rl0) c0 = -1e30f;
                if (col + 1 > rl0) c1 = -1e30f;
                if (col     > rl1) c2 = -1e30f;
                if (col + 1 > rl1) c3 = -1e30f;
            }
            sc[nf][0] = c0; sc[nf][1] = c1; sc[nf][2] = c2; sc[nf][3] = c3;
            rm0 = fmaxf(rm0, fmaxf(c0, c1));
            rm1 = fmaxf(rm1, fmaxf(c2, c3));
        }
        rm0 = fmaxf(rm0, __shfl_xor_sync(0xffffffffu, rm0, 1));
        rm0 = fmaxf(rm0, __shfl_xor_sync(0xffffffffu, rm0, 2));
        rm1 = fmaxf(rm1, __shfl_xor_sync(0xffffffffu, rm1, 1));
        rm1 = fmaxf(rm1, __shfl_xor_sync(0xffffffffu, rm1, 2));

        const float mn0 = fmaxf(m0, rm0), mn1 = fmaxf(m1, rm1);
        const float a0 = __expf(m0 - mn0), a1 = __expf(m1 - mn1);
        float rs0 = 0.0f, rs1 = 0.0f;
#pragma unroll
        for (int nf = 0; nf < 16; nf++) {
            float p0 = __expf(sc[nf][0] - mn0);
            float p1 = __expf(sc[nf][1] - mn0);
            float p2 = __expf(sc[nf][2] - mn1);
            float p3 = __expf(sc[nf][3] - mn1);
            sc[nf][0] = p0; sc[nf][1] = p1; sc[nf][2] = p2; sc[nf][3] = p3;
            rs0 += p0 + p1;
            rs1 += p2 + p3;
        }
        rs0 += __shfl_xor_sync(0xffffffffu, rs0, 1);
        rs0 += __shfl_xor_sync(0xffffffffu, rs0, 2);
        rs1 += __shfl_xor_sync(0xffffffffu, rs1, 1);
        rs1 += __shfl_xor_sync(0xffffffffu, rs1, 2);
        l0 = l0 * a0 + rs0;
        l1 = l1 * a1 + rs1;
        m0 = mn0;
        m1 = mn1;
#pragma unroll
        for (int nd = 0; nd < 8; nd++) {
            o[nd][0] *= a0; o[nd][1] *= a0;
            o[nd][2] *= a1; o[nd][3] *= a1;
        }

        // ---- O += P V (3-term split; P from registers) ----
#pragma unroll
        for (int kk = 0; kk < 8; kk++) {
            float* p0 = sc[2 * kk];
            float* p1 = sc[2 * kk + 1];
            uint32_t phi[4], plo[4];
            phi[0] = pack_bf2(p0[0], p0[1]);
            phi[1] = pack_bf2(p0[2], p0[3]);
            phi[2] = pack_bf2(p1[0], p1[1]);
            phi[3] = pack_bf2(p1[2], p1[3]);
            plo[0] = pack_bf2(bf_res(p0[0]), bf_res(p0[1]));
            plo[1] = pack_bf2(bf_res(p0[2]), bf_res(p0[3]));
            plo[2] = pack_bf2(bf_res(p1[0]), bf_res(p1[1]));
            plo[3] = pack_bf2(bf_res(p1[2]), bf_res(p1[3]));
#pragma unroll
            for (int df = 0; df < 4; df++) {
                const int db = df * 32 + lc16;
                uint32_t t[4], u[4];
                ldm_x4_t(t, swz(vhiS, kk * 16 + lrow, db));
                ldm_x4_t(u, swz(vloS, kk * 16 + lrow, db));
                uint32_t vh0[2] = {t[0], t[1]}, vh1[2] = {t[2], t[3]};
                uint32_t vl0[2] = {u[0], u[1]}, vl1[2] = {u[2], u[3]};
                mma16816(o[2 * df],     phi, vh0);
                mma16816(o[2 * df],     phi, vl0);
                mma16816(o[2 * df],     plo, vh0);
                mma16816(o[2 * df + 1], phi, vh1);
                mma16816(o[2 * df + 1], phi, vl1);
                mma16816(o[2 * df + 1], plo, vh1);
            }
        }
        __syncthreads();   // all warps done with stage s before overwrite
    }

    // ---- epilogue: normalize, split to bf16 hi/lo ----
    const float inv0 = 1.0f / l0;
    const float inv1 = 1.0f / l1;
    const size_t r0 = rowQ + wid * 16 + g;
    const size_t r1 = r0 + 8;
#pragma unroll
    for (int nd = 0; nd < 8; nd++) {
        int col = h * DD + nd * 8 + t2;
        float v0 = o[nd][0] * inv0, v1 = o[nd][1] * inv0;
        float v2 = o[nd][2] * inv1, v3 = o[nd][3] * inv1;
        size_t i0 = (r0 * CC + col) >> 1;
        size_t i1 = (r1 * CC + col) >> 1;
        ((uint32_t*)ohi)[i0] = pack_bf2(v0, v1);
        ((uint32_t*)olo)[i0] = pack_bf2(bf_res(v0), bf_res(v1));
        ((uint32_t*)ohi)[i1] = pack_bf2(v2, v3);
        ((uint32_t*)olo)[i1] = pack_bf2(bf_res(v2), bf_res(v3));
    }
}

// ---------------------------------------------------------------------------
// Launch
// ---------------------------------------------------------------------------
extern "C" void kernel_launch(void* const* d_in, const int* in_sizes, int n_in,
                              void* d_out, int out_size)
{
    (void)in_sizes; (void)n_in; (void)out_size;
    const float* x      = (const float*)d_in[0];
    const float* w_attn = (const float*)d_in[1];
    const float* b_attn = (const float*)d_in[2];
    const float* w_proj = (const float*)d_in[3];
    const float* b_proj = (const float*)d_in[4];
    float* out = (float*)d_out;

    __nv_bfloat16 *xhi, *xlo, *wahi, *walo, *wphi, *wplo;
    __nv_bfloat16 *qkvhi, *qkvlo, *ahi, *alo;
    cudaGetSymbolAddress((void**)&xhi,   g_xhi);
    cudaGetSymbolAddress((void**)&xlo,   g_xlo);
    cudaGetSymbolAddress((void**)&wahi,  g_wahi);
    cudaGetSymbolAddress((void**)&walo,  g_walo);
    cudaGetSymbolAddress((void**)&wphi,  g_wphi);
    cudaGetSymbolAddress((void**)&wplo,  g_wplo);
    cudaGetSymbolAddress((void**)&qkvhi, g_qkvhi);
    cudaGetSymbolAddress((void**)&qkvlo, g_qkvlo);
    cudaGetSymbolAddress((void**)&ahi,   g_ahi);
    cudaGetSymbolAddress((void**)&alo,   g_alo);

    cudaFuncSetAttribute(gemm_mma_kernel,
                         cudaFuncAttributeMaxDynamicSharedMemorySize, GEMM_SMEM);
    cudaFuncSetAttribute(flash_mma_kernel,
                         cudaFuncAttributeMaxDynamicSharedMemorySize, FLASH_SMEM);

    // 1) split x -> bf16 hi/lo
    {
        int n4 = NTOK * CC / 4;
        split_fp32_kernel<<<(n4 + 255) / 256, 256>>>(x, xhi, xlo, n4);
    }
    // 2) split+transpose weights -> [N,K] bf16 hi/lo
    {
        dim3 blk(32, 8);
        split_transpose_kernel<<<dim3(QKVN / 32, CC / 32), blk>>>(w_attn, wahi, walo, CC, QKVN);
        split_transpose_kernel<<<dim3(CC / 32, CC / 32), blk>>>(w_proj, wphi, wplo, CC, CC);
    }
    // 3) QKV GEMM -> split bf16 hi/lo qkv
    {
        dim3 grid(QKVN / 128, NTOK / 128);
        gemm_mma_kernel<<<grid, 256, GEMM_SMEM>>>(xhi, xlo, wahi, walo,
                                                  b_attn, nullptr, qkvhi, qkvlo,
                                                  NTOK, QKVN, CC);
    }
    // 4) tensor-core flash attention -> split bf16 hi/lo y
    {
        dim3 grid(TT / 128, BB * HH);
        flash_mma_kernel<<<grid, 256, FLASH_SMEM>>>(qkvhi, qkvlo, ahi, alo);
    }
    // 5) proj GEMM -> fp32 out
    {
        dim3 grid(CC / 128, NTOK / 128);
        gemm_mma_kernel<<<grid, 256, GEMM_SMEM>>>(ahi, alo, wphi, wplo,
                                                  b_proj, out, nullptr, nullptr,
                                                  NTOK, CC, CC);
    }
}